// round 1
// baseline (speedup 1.0000x reference)
#include <cuda_runtime.h>

// GNN sudoku model, fully fused.
// h kept in shared memory per CTA (2 boards), 6 GCN layers:
//   h <- relu( (A_norm h) W_l + b_l ),  A_norm = (structured sudoku adjacency)/21
// A-op done via row/col/box partial sums (inclusion-exclusion), in place.
// GEMM (192x128x128 per CTA per layer) with register-resident accumulators
// using packed fma.rn.f32x2 (Blackwell f32x2 pipe, 2 FMA/lane/instr).

#define NNODES     81
#define HDIM       128
#define NLAYERS    6
#define BC         2          // boards per CTA
#define ITEM_STRIDE 96        // board stride inside an hT row (16B aligned)
#define HT_STRIDE  196        // floats per hT row (==4 mod 32 -> conflict-free float4 phases)
#define THREADS    256
#define MTILE      24         // m-columns per thread in GEMM (8 tm groups * 24 = 192)

#define SMEM_HT_FLOATS  (HDIM * HT_STRIDE)      // 25088
#define SMEM_W_FLOATS   (HDIM * HDIM)           // 16384
#define SMEM_B_FLOATS   (HDIM)                  // 128
#define SMEM_X_INTS     176
#define SMEM_BYTES  ((SMEM_HT_FLOATS + SMEM_W_FLOATS + SMEM_B_FLOATS) * 4 + SMEM_X_INTS * 4)

// ---------- packed f32x2 helpers ----------
__device__ __forceinline__ unsigned long long pk2(float lo, float hi) {
    unsigned long long r;
    asm("mov.b64 %0, {%1, %2};" : "=l"(r) : "f"(lo), "f"(hi));
    return r;
}
__device__ __forceinline__ void fma2(unsigned long long& d, unsigned long long a,
                                     unsigned long long b) {
    asm("fma.rn.f32x2 %0, %1, %2, %0;" : "+l"(d) : "l"(a), "l"(b));
}
__device__ __forceinline__ void upk2(unsigned long long v, float& lo, float& hi) {
    asm("mov.b64 {%0, %1}, %2;" : "=f"(lo), "=f"(hi) : "l"(v));
}

// ---------- structured A_norm multiply, in place on one 81-float row ----------
// out[i,j] = (RS[i] + CS[j] + BS[i/3,j/3] - Trow[i,j/3] - Tcol[i/3,j]) / 21
__device__ __forceinline__ void sudoku_aop(float* __restrict__ row) {
    float Trow[9][3];
    float Tcol[3][9];
#pragma unroll
    for (int i = 0; i < 9; i++) { Trow[i][0] = 0.f; Trow[i][1] = 0.f; Trow[i][2] = 0.f; }
#pragma unroll
    for (int j = 0; j < 9; j++) { Tcol[0][j] = 0.f; Tcol[1][j] = 0.f; Tcol[2][j] = 0.f; }

#pragma unroll
    for (int q = 0; q < 20; q++) {
        float4 v = *(const float4*)(row + 4 * q);
        float vv[4] = {v.x, v.y, v.z, v.w};
#pragma unroll
        for (int e = 0; e < 4; e++) {
            const int idx = 4 * q + e;
            const int i = idx / 9, j = idx - i * 9;
            Trow[i][j / 3] += vv[e];
            Tcol[i / 3][j] += vv[e];
        }
    }
    {
        float v = row[80];
        Trow[8][2] += v;
        Tcol[2][8] += v;
    }

    float RS[9], CS[9], BS[3][3];
#pragma unroll
    for (int i = 0; i < 9; i++) RS[i] = Trow[i][0] + Trow[i][1] + Trow[i][2];
#pragma unroll
    for (int j = 0; j < 9; j++) CS[j] = Tcol[0][j] + Tcol[1][j] + Tcol[2][j];
#pragma unroll
    for (int bi = 0; bi < 3; bi++)
#pragma unroll
        for (int bj = 0; bj < 3; bj++)
            BS[bi][bj] = Trow[3 * bi][bj] + Trow[3 * bi + 1][bj] + Trow[3 * bi + 2][bj];

    const float inv21 = 1.0f / 21.0f;
#pragma unroll
    for (int q = 0; q < 20; q++) {
        float o[4];
#pragma unroll
        for (int e = 0; e < 4; e++) {
            const int idx = 4 * q + e;
            const int i = idx / 9, j = idx - i * 9;
            o[e] = (RS[i] + CS[j] + BS[i / 3][j / 3] - Trow[i][j / 3] - Tcol[i / 3][j]) * inv21;
        }
        float4 vo;
        vo.x = o[0]; vo.y = o[1]; vo.z = o[2]; vo.w = o[3];
        *(float4*)(row + 4 * q) = vo;
    }
    row[80] = (RS[8] + CS[8] + BS[2][2] - Trow[8][2] - Tcol[2][8]) * inv21;
}

__global__ void __launch_bounds__(THREADS, 1)
gnn_kernel(const long long* __restrict__ xraw,
           const float* __restrict__ Win,  const float* __restrict__ bin,
           const float* __restrict__ Wlay, const float* __restrict__ blay,
           const float* __restrict__ Wout, const float* __restrict__ bout,
           float* __restrict__ out) {
    extern __shared__ float smem[];
    float* hT  = smem;                                  // [128][196]
    float* Wsm = smem + SMEM_HT_FLOATS;                 // [128][128] (also W_in / W_out staging)
    float* bsm = Wsm + SMEM_W_FLOATS;                   // [128]
    int*   xs  = (int*)(bsm + SMEM_B_FLOATS);           // [176]

    const int t = threadIdx.x;
    const long long itembase = (long long)blockIdx.x * BC;

    // ---- detect whether x is int64 or int32 (jax x64 may be disabled) ----
    long long probe = (t < 162) ? xraw[t] : 0;          // reads first 1296B of x: safe either way
    const int is32 = __syncthreads_or(probe > 9 || probe < 0);

    // ---- load x for this CTA ----
    for (int i = t; i < BC * NNODES; i += THREADS) {
        long long g = itembase * NNODES + i;
        xs[i] = is32 ? ((const int*)xraw)[g] : (int)xraw[g];
    }
    // ---- W_in (10x128) + b_in ----
    for (int i = t; i < 10 * HDIM; i += THREADS) Wsm[i] = Win[i];
    if (t < HDIM) bsm[t] = bin[t];
    // ---- zero hT (covers pad columns; valid region overwritten below) ----
    for (int i = t; i < SMEM_HT_FLOATS; i += THREADS) hT[i] = 0.f;
    __syncthreads();

    // ---- h0 = relu(W_in[x] + b_in), feature-major layout hT[k][item*96+node] ----
    {
        const int k = t & (HDIM - 1), item = t >> 7;
        const float bk = bsm[k];
        float* row = hT + k * HT_STRIDE + item * ITEM_STRIDE;
        const int* xr = xs + item * NNODES;
#pragma unroll 4
        for (int q = 0; q < 20; q++) {
            float4 o;
            o.x = fmaxf(Wsm[xr[4 * q + 0] * HDIM + k] + bk, 0.f);
            o.y = fmaxf(Wsm[xr[4 * q + 1] * HDIM + k] + bk, 0.f);
            o.z = fmaxf(Wsm[xr[4 * q + 2] * HDIM + k] + bk, 0.f);
            o.w = fmaxf(Wsm[xr[4 * q + 3] * HDIM + k] + bk, 0.f);
            *(float4*)(row + 4 * q) = o;
        }
        row[80] = fmaxf(Wsm[xr[80] * HDIM + k] + bk, 0.f);
    }

    const int tn = t & 31;          // n group: columns tn, tn+32, tn+64, tn+96
    const int m0 = (t >> 5) * MTILE;

    for (int l = 0; l < NLAYERS; l++) {
        __syncthreads();
        // ---- stage W_l, b_l (overlaps A-op below) ----
        {
            const float4* Wg = (const float4*)(Wlay + l * HDIM * HDIM);
            for (int i = t; i < (HDIM * HDIM) / 4; i += THREADS) ((float4*)Wsm)[i] = Wg[i];
            if (t < HDIM) bsm[t] = blay[l * HDIM + t];
        }
        // ---- g = A_norm h, in place (thread owns one (feature, board) row) ----
        sudoku_aop(hT + (t & (HDIM - 1)) * HT_STRIDE + (t >> 7) * ITEM_STRIDE);
        __syncthreads();

        // ---- h = relu(g W + b): M=192(pad of 162) x N=128 x K=128 ----
        unsigned long long acc[4][12];
#pragma unroll
        for (int nn = 0; nn < 4; nn++)
#pragma unroll
            for (int p = 0; p < 12; p++) acc[nn][p] = 0ULL;

        const float* hbase = hT + m0;
        const float* wbase = Wsm + tn;
#pragma unroll 4
        for (int k = 0; k < HDIM; k++) {
            const float4* hp = (const float4*)(hbase + k * HT_STRIDE);
            float4 a0 = hp[0], a1 = hp[1], a2 = hp[2], a3 = hp[3], a4 = hp[4], a5 = hp[5];
            unsigned long long hp01[12];
            hp01[0]  = pk2(a0.x, a0.y); hp01[1]  = pk2(a0.z, a0.w);
            hp01[2]  = pk2(a1.x, a1.y); hp01[3]  = pk2(a1.z, a1.w);
            hp01[4]  = pk2(a2.x, a2.y); hp01[5]  = pk2(a2.z, a2.w);
            hp01[6]  = pk2(a3.x, a3.y); hp01[7]  = pk2(a3.z, a3.w);
            hp01[8]  = pk2(a4.x, a4.y); hp01[9]  = pk2(a4.z, a4.w);
            hp01[10] = pk2(a5.x, a5.y); hp01[11] = pk2(a5.z, a5.w);
            const float* wp = wbase + k * HDIM;
            const float w0s = wp[0], w1s = wp[32], w2s = wp[64], w3s = wp[96];
            const unsigned long long w0 = pk2(w0s, w0s), w1 = pk2(w1s, w1s);
            const unsigned long long w2 = pk2(w2s, w2s), w3 = pk2(w3s, w3s);
#pragma unroll
            for (int p = 0; p < 12; p++) {
                fma2(acc[0][p], hp01[p], w0);
                fma2(acc[1][p], hp01[p], w1);
                fma2(acc[2][p], hp01[p], w2);
                fma2(acc[3][p], hp01[p], w3);
            }
        }
        __syncthreads();

        // ---- writeback relu(acc + b) into hT (pad columns written too: harmless) ----
#pragma unroll
        for (int nn = 0; nn < 4; nn++) {
            const int rowi = tn + 32 * nn;
            const float bb = bsm[rowi];
            float* wr = hT + rowi * HT_STRIDE + m0;
#pragma unroll
            for (int q = 0; q < 6; q++) {
                float x0, x1, x2, x3;
                upk2(acc[nn][2 * q],     x0, x1);
                upk2(acc[nn][2 * q + 1], x2, x3);
                float4 o;
                o.x = fmaxf(x0 + bb, 0.f);
                o.y = fmaxf(x1 + bb, 0.f);
                o.z = fmaxf(x2 + bb, 0.f);
                o.w = fmaxf(x3 + bb, 0.f);
                *(float4*)(wr + 4 * q) = o;
            }
        }
    }

    __syncthreads();
    // ---- logits = h W_out + b_out, direct to gmem ----
    for (int i = t; i < HDIM * 9; i += THREADS) Wsm[i] = Wout[i];
    if (t < 9) bsm[t] = bout[t];
    __syncthreads();

    for (int idx = t; idx < BC * NNODES * 9; idx += THREADS) {
        const int item = idx / (NNODES * 9);
        const int r = idx - item * (NNODES * 9);
        const int node = r / 9, j = r - node * 9;
        const float* hcol = hT + item * ITEM_STRIDE + node;
        float s = bsm[j];
#pragma unroll 8
        for (int k = 0; k < HDIM; k++) s += hcol[k * HT_STRIDE] * Wsm[k * 9 + j];
        out[itembase * (NNODES * 9) + idx] = s;
    }
}

extern "C" void kernel_launch(void* const* d_in, const int* in_sizes, int n_in,
                              void* d_out, int out_size) {
    (void)in_sizes; (void)n_in; (void)out_size;
    cudaFuncSetAttribute(gnn_kernel, cudaFuncAttributeMaxDynamicSharedMemorySize, SMEM_BYTES);
    const int nctas = 8192 / BC;
    gnn_kernel<<<nctas, THREADS, SMEM_BYTES>>>(
        (const long long*)d_in[0],
        (const float*)d_in[1], (const float*)d_in[2],
        (const float*)d_in[3], (const float*)d_in[4],
        (const float*)d_in[5], (const float*)d_in[6],
        (float*)d_out);
}

// round 4
// speedup vs baseline: 1.5573x; 1.5573x over previous
#include <cuda_runtime.h>
#include <cuda_fp16.h>
#include <cstdint>

// Fused sudoku-GNN, mma.sync (HMMA) tensor-core path for baseline sm_100 target.
// Per CTA: 2 boards. h kept fp32 in smem (feature-major). Per layer:
//   g = A_norm h   (structured inclusion-exclusion, in place)
//   h = relu(g W + b) via split-fp16 mma.sync: g=hi+lo, W=Hi+Lo,
//   terms hi*Hi + hi*Lo + lo*Hi accumulated in fp32 fragments (~1e-6 accurate).
// Phase1: Ahi x {Whi,Wlo} (both W halves resident, cp.async'd under the A-op).
// Then A reconverted in place to Alo; Phase2: Alo x Whi.

#define NLAYERS 6
#define HDIM    128
#define NNODES  81
#define BC      2

#define HT_STRIDE 172          // fp32 per hT row; 688B = 43*16 -> conflict-free float4
#define HT_BOFF   84           // board offset inside a row (336B, 16B aligned)
#define A_STRIDE  136          // fp16 per A row; 272B = 17*16 -> conflict-free ldmatrix
#define W_STRIDE  136

// ---- smem byte offsets ----
#define SM_HT   0                               // 128*172*4 = 88064
#define SM_A    88064                           // 192*136*2 = 52224
#define SM_W1   140288                          // Whi 128*136*2 = 34816
#define SM_W2   175104                          // Wlo 34816
#define SM_BIAS 209920                          // 128 fp32
#define SM_XS   210432                          // 162 ints
#define SMEM_BYTES 211200

// pre-split padded weights in gmem: [n][k] fp16, stride 136
__device__ __align__(16) unsigned char g_Wh[NLAYERS][34816];
__device__ __align__(16) unsigned char g_Wl[NLAYERS][34816];

__device__ __forceinline__ uint32_t smem_u32(const void* p) {
    uint32_t a;
    asm("{ .reg .u64 t; cvta.to.shared.u64 t, %1; cvt.u32.u64 %0, t; }" : "=r"(a) : "l"(p));
    return a;
}
#define CPA16(dst, src) asm volatile("cp.async.cg.shared.global [%0], [%1], 16;" :: "r"(dst), "l"(src))
#define CPA_COMMIT()    asm volatile("cp.async.commit_group;" ::: "memory")
#define CPA_WAIT0()     asm volatile("cp.async.wait_group 0;" ::: "memory")

#define LDMX4(r, addr)                                                        \
    asm volatile("ldmatrix.sync.aligned.m8n8.x4.shared.b16 {%0,%1,%2,%3}, [%4];" \
        : "=r"((r)[0]), "=r"((r)[1]), "=r"((r)[2]), "=r"((r)[3]) : "r"(addr))
#define LDMX2(r, addr)                                                        \
    asm volatile("ldmatrix.sync.aligned.m8n8.x2.shared.b16 {%0,%1}, [%2];"    \
        : "=r"((r)[0]), "=r"((r)[1]) : "r"(addr))
#define MMA16816(d, a, b)                                                     \
    asm volatile("mma.sync.aligned.m16n8k16.row.col.f32.f16.f16.f32 "         \
        "{%0,%1,%2,%3},{%4,%5,%6,%7},{%8,%9},{%0,%1,%2,%3};"                  \
        : "+f"((d)[0]), "+f"((d)[1]), "+f"((d)[2]), "+f"((d)[3])              \
        : "r"((a)[0]), "r"((a)[1]), "r"((a)[2]), "r"((a)[3]),                 \
          "r"((b)[0]), "r"((b)[1]))

// ---------- prep: split W layers to padded fp16 hi/lo [n][k] ----------
__global__ void prep_kernel(const float* __restrict__ Wlay) {
    int t = blockIdx.x * blockDim.x + threadIdx.x;
    if (t >= NLAYERS * HDIM * HDIM) return;
    int l = t >> 14, r = t & 16383, k = r >> 7, n = r & 127;
    float w = Wlay[t];                      // Wlay[l][k][n]
    __half hi = __float2half_rn(w);
    __half lo = __float2half_rn(w - __half2float(hi));
    uint32_t off = ((uint32_t)n * W_STRIDE + (uint32_t)k) * 2;
    *(__half*)(g_Wh[l] + off) = hi;
    *(__half*)(g_Wl[l] + off) = lo;
}

// ---------- structured A_norm multiply on one 81-float row ----------
// Computes g in place AND writes fp16(hi) of g into the A operand buffer.
__device__ __forceinline__ void sudoku_aop_to_A(float* __restrict__ row,
                                                unsigned char* __restrict__ smA,
                                                int f, int mbase) {
    float Trow[9][3], Tcol[3][9];
#pragma unroll
    for (int i = 0; i < 9; i++) { Trow[i][0] = Trow[i][1] = Trow[i][2] = 0.f; }
#pragma unroll
    for (int j = 0; j < 9; j++) { Tcol[0][j] = Tcol[1][j] = Tcol[2][j] = 0.f; }
#pragma unroll
    for (int q = 0; q < 20; q++) {
        float4 v = *(const float4*)(row + 4 * q);
        float vv[4] = {v.x, v.y, v.z, v.w};
#pragma unroll
        for (int e = 0; e < 4; e++) {
            const int idx = 4 * q + e, i = idx / 9, j = idx - 9 * i;
            Trow[i][j / 3] += vv[e];
            Tcol[i / 3][j] += vv[e];
        }
    }
    { float v = row[80]; Trow[8][2] += v; Tcol[2][8] += v; }

    float RS[9], CS[9], BS[3][3];
#pragma unroll
    for (int i = 0; i < 9; i++) RS[i] = Trow[i][0] + Trow[i][1] + Trow[i][2];
#pragma unroll
    for (int j = 0; j < 9; j++) CS[j] = Tcol[0][j] + Tcol[1][j] + Tcol[2][j];
#pragma unroll
    for (int bi = 0; bi < 3; bi++)
#pragma unroll
        for (int bj = 0; bj < 3; bj++)
            BS[bi][bj] = Trow[3 * bi][bj] + Trow[3 * bi + 1][bj] + Trow[3 * bi + 2][bj];

    const float inv21 = 1.0f / 21.0f;
#pragma unroll
    for (int node = 0; node < NNODES; node++) {
        const int i = node / 9, j = node - 9 * i;
        float g = (RS[i] + CS[j] + BS[i / 3][j / 3]
                   - Trow[i][j / 3] - Tcol[i / 3][j]) * inv21;
        row[node] = g;
        *(__half*)(smA + (((uint32_t)(mbase + node)) * A_STRIDE + f) * 2) =
            __float2half_rn(g);
    }
}

__global__ void __launch_bounds__(256)
gnn_mma(const long long* __restrict__ xraw,
        const float* __restrict__ Win,  const float* __restrict__ bin,
        const float* __restrict__ blay, const float* __restrict__ bout,
        const float* __restrict__ Wout, float* __restrict__ out) {
    extern __shared__ unsigned char smem[];
    float* hT = (float*)(smem + SM_HT);
    const int t = threadIdx.x, wid = t >> 5, lane = t & 31;
    const uint32_t sbase = smem_u32(smem);

    // ---- zero A buffer (pad rows must stay clean across all layers) ----
    for (int i = t * 16; i < 52224; i += 256 * 16)
        *(uint4*)(smem + SM_A + i) = make_uint4(0, 0, 0, 0);

    // ---- x load (int64 vs int32 robust) ----
    long long probe = (t < 162) ? xraw[t] : 0;
    const int is32 = __syncthreads_or(probe > 9 || probe < 0);
    {
        const long long gbase = (long long)blockIdx.x * BC * NNODES;
        for (int i = t; i < BC * NNODES; i += 256)
            ((int*)(smem + SM_XS))[i] =
                is32 ? ((const int*)xraw)[gbase + i] : (int)xraw[gbase + i];
    }
    // ---- Win staged into A region (alias; dead before first aop write) ----
    for (int i = t; i < 10 * HDIM; i += 256)
        ((float*)(smem + SM_A))[i] = Win[i];
    __syncthreads();

    // ---- h0 = relu(Win[x] + b_in) into hT (feature-major) ----
    {
        const int f = t & 127, b = t >> 7;
        const float bk = bin[f];
        const float* Wi = (const float*)(smem + SM_A);
        const int* xr = (const int*)(smem + SM_XS) + b * NNODES;
        float* row = hT + f * HT_STRIDE + b * HT_BOFF;
#pragma unroll 9
        for (int node = 0; node < NNODES; node++)
            row[node] = fmaxf(Wi[xr[node] * HDIM + f] + bk, 0.f);
    }
    __syncthreads();

    // ---- per-warp GEMM geometry ----
    const int m0 = (wid & 3) * 48;           // 3 m16 tiles
    const int n0 = (wid >> 2) * 64;          // 8 n8 tiles
    const uint32_t aBase = sbase + SM_A +
        (((uint32_t)(m0 + (lane & 15))) * A_STRIDE + (uint32_t)((lane >> 4) * 8)) * 2;
    const uint32_t bOff =
        (((uint32_t)(n0 + (lane & 7))) * W_STRIDE + (uint32_t)(((lane >> 3) & 1) * 8)) * 2;
    const uint32_t b1Base = sbase + SM_W1 + bOff;
    const uint32_t b2Base = sbase + SM_W2 + bOff;

    const int fA = t & 127, bA = t >> 7;     // aop/convert ownership
    float* aopRow = hT + fA * HT_STRIDE + bA * HT_BOFF;
    unsigned char* smA = smem + SM_A;
    const int mbase = bA * 96;

    for (int l = 0; l < NLAYERS; l++) {
        // ---- cp.async both W halves + bias; overlap with aop ----
        {
            const unsigned char* sh = g_Wh[l];
            const unsigned char* sl = g_Wl[l];
            for (int i = t * 16; i < 34816; i += 256 * 16) {
                CPA16(sbase + SM_W1 + i, sh + i);
                CPA16(sbase + SM_W2 + i, sl + i);
            }
            if (t < 32) CPA16(sbase + SM_BIAS + t * 16,
                              (const unsigned char*)(blay + l * HDIM) + t * 16);
            CPA_COMMIT();
        }
        // ---- aop: g in place + Ahi into A ----
        sudoku_aop_to_A(aopRow, smA, fA, mbase);
        CPA_WAIT0();
        __syncthreads();

        // ---- Phase 1: Ahi x Whi + Ahi x Wlo ----
        float acc[3][8][4];
#pragma unroll
        for (int ti = 0; ti < 3; ti++)
#pragma unroll
            for (int tj = 0; tj < 8; tj++)
#pragma unroll
                for (int e = 0; e < 4; e++) acc[ti][tj][e] = 0.f;

#pragma unroll
        for (int ks = 0; ks < 8; ks++) {
            const uint32_t ko = ks * 32;            // 16 halves * 2B
            uint32_t b1[8][2], b2[8][2];
#pragma unroll
            for (int tj = 0; tj < 8; tj++) {
                LDMX2(b1[tj], b1Base + tj * (8 * W_STRIDE * 2) + ko);
                LDMX2(b2[tj], b2Base + tj * (8 * W_STRIDE * 2) + ko);
            }
#pragma unroll
            for (int ti = 0; ti < 3; ti++) {
                uint32_t a[4];
                LDMX4(a, aBase + ti * (16 * A_STRIDE * 2) + ko);
#pragma unroll
                for (int tj = 0; tj < 8; tj++) MMA16816(acc[ti][tj], a, b1[tj]);
#pragma unroll
                for (int tj = 0; tj < 8; tj++) MMA16816(acc[ti][tj], a, b2[tj]);
            }
        }
        __syncthreads();

        // ---- reconvert A in place: Alo = g - fp16(g) ----
        {
#pragma unroll 9
            for (int node = 0; node < NNODES; node++) {
                float g = aopRow[node];
                float hi = __half2float(__float2half_rn(g));
                *(__half*)(smA + (((uint32_t)(mbase + node)) * A_STRIDE + fA) * 2) =
                    __float2half_rn(g - hi);
            }
        }
        __syncthreads();

        // ---- Phase 2: Alo x Whi ----
#pragma unroll
        for (int ks = 0; ks < 8; ks++) {
            const uint32_t ko = ks * 32;
            uint32_t b1[8][2];
#pragma unroll
            for (int tj = 0; tj < 8; tj++)
                LDMX2(b1[tj], b1Base + tj * (8 * W_STRIDE * 2) + ko);
#pragma unroll
            for (int ti = 0; ti < 3; ti++) {
                uint32_t a[4];
                LDMX4(a, aBase + ti * (16 * A_STRIDE * 2) + ko);
#pragma unroll
                for (int tj = 0; tj < 8; tj++) MMA16816(acc[ti][tj], a, b1[tj]);
            }
        }
        __syncthreads();

        // ---- epilogue: h = relu(acc + bias) -> hT (transposed store) ----
        {
            const float* bias = (const float*)(smem + SM_BIAS);
#pragma unroll
            for (int ti = 0; ti < 3; ti++) {
                const int r0 = m0 + 16 * ti + (lane >> 2);
#pragma unroll
                for (int tj = 0; tj < 8; tj++) {
                    const int c0 = n0 + 8 * tj + 2 * (lane & 3);
                    const float bb0 = bias[c0], bb1 = bias[c0 + 1];
#pragma unroll
                    for (int half_ = 0; half_ < 2; half_++) {
                        const int r = r0 + 8 * half_;
                        const int board = r / 96, node = r - 96 * board;
                        if (node < NNODES) {
                            const int base = c0 * HT_STRIDE + board * HT_BOFF + node;
                            hT[base] =
                                fmaxf(acc[ti][tj][2 * half_] + bb0, 0.f);
                            hT[base + HT_STRIDE] =
                                fmaxf(acc[ti][tj][2 * half_ + 1] + bb1, 0.f);
                        }
                    }
                }
            }
        }
        __syncthreads();
    }

    // ---- output layer: logits = h Wout + bout, direct from hT ----
    {
        float* Wsm = (float*)(smem + SM_W1);
        for (int i = t; i < HDIM * 9; i += 256) Wsm[i] = Wout[i];
        if (t < 9) ((float*)(smem + SM_BIAS))[t] = bout[t];
        __syncthreads();
        const float* bsm = (const float*)(smem + SM_BIAS);
        const long long obase = (long long)blockIdx.x * (BC * NNODES * 9);
        for (int idx = t; idx < BC * NNODES * 9; idx += 256) {
            const int item = idx / (NNODES * 9);
            const int r = idx - item * (NNODES * 9);
            const int node = r / 9, j = r - node * 9;
            const float* hcol = hT + item * HT_BOFF + node;
            float s = bsm[j];
#pragma unroll 8
            for (int k = 0; k < HDIM; k++) s += hcol[k * HT_STRIDE] * Wsm[k * 9 + j];
            out[obase + idx] = s;
        }
    }
}

extern "C" void kernel_launch(void* const* d_in, const int* in_sizes, int n_in,
                              void* d_out, int out_size) {
    (void)in_sizes; (void)n_in; (void)out_size;
    prep_kernel<<<384, 256>>>((const float*)d_in[3]);
    cudaFuncSetAttribute(gnn_mma, cudaFuncAttributeMaxDynamicSharedMemorySize, SMEM_BYTES);
    gnn_mma<<<8192 / BC, 256, SMEM_BYTES>>>(
        (const long long*)d_in[0],
        (const float*)d_in[1], (const float*)d_in[2],
        (const float*)d_in[4], (const float*)d_in[6],
        (const float*)d_in[5], (float*)d_out);
}

// round 5
// speedup vs baseline: 1.8925x; 1.2152x over previous
#include <cuda_runtime.h>
#include <cuda_fp16.h>
#include <cstdint>

// Fused sudoku-GNN, split-fp16 HMMA (mma.sync m16n8k16), single-pass version.
// h lives ONLY as fp16 (hi,lo) pairs in two MMA-operand smem buffers.
// Per layer: aop (in-register inclusion-exclusion per (feature,board) column,
// in place) -> one MMA pass accumulating hi*Whi + hi*Wlo + lo*Whi ->
// epilogue relu(acc+b) split back to (hi,lo). Output layer is one more MMA
// against zero-padded WoutT. No fp32 h buffer, 3 barriers/layer.

#define NLAYERS 6
#define HDIM    128
#define NNODES  81
#define BC      2
#define A_STRIDE 136     // halves per A row (272B; 8 rows cover distinct 16B banks)
#define W_STRIDE 136

// ---- smem byte offsets ----
#define SM_A1    0            // h/g hi  [192][136] fp16 = 52224
#define SM_A2    52224        // h/g lo
#define SM_W1    104448       // W hi [128][136] fp16 = 34816
#define SM_W2    139264       // W lo
#define SM_BIAS0 174080       // 128 fp32 (ping)
#define SM_BIAS1 174592       // 128 fp32 (pong)
#define SM_STAGE 175104       // 5888B: Win staging (5120) / logits (5832)... logits 5832 > 5888? no: 5832 <= 5888 ok
#define SM_XS    180992       // 162 ints
#define SMEM_BYTES 181760

__device__ __align__(16) unsigned char g_Wh[NLAYERS][34816];
__device__ __align__(16) unsigned char g_Wl[NLAYERS][34816];
__device__ __align__(16) unsigned char g_WoH[4352];   // WoutT padded [16][136]
__device__ __align__(16) unsigned char g_WoL[4352];

__device__ __forceinline__ uint32_t smem_u32(const void* p) {
    uint32_t a;
    asm("{ .reg .u64 t; cvta.to.shared.u64 t, %1; cvt.u32.u64 %0, t; }" : "=r"(a) : "l"(p));
    return a;
}
#define CPA16(dst, src) asm volatile("cp.async.cg.shared.global [%0], [%1], 16;" :: "r"(dst), "l"(src))
#define CPA_COMMIT()    asm volatile("cp.async.commit_group;" ::: "memory")
#define CPA_WAIT0()     asm volatile("cp.async.wait_group 0;" ::: "memory")

#define LDMX4(r, addr)                                                        \
    asm volatile("ldmatrix.sync.aligned.m8n8.x4.shared.b16 {%0,%1,%2,%3}, [%4];" \
        : "=r"((r)[0]), "=r"((r)[1]), "=r"((r)[2]), "=r"((r)[3]) : "r"(addr))
#define MMA16816(d, a, b)                                                     \
    asm volatile("mma.sync.aligned.m16n8k16.row.col.f32.f16.f16.f32 "         \
        "{%0,%1,%2,%3},{%4,%5,%6,%7},{%8,%9},{%0,%1,%2,%3};"                  \
        : "+f"((d)[0]), "+f"((d)[1]), "+f"((d)[2]), "+f"((d)[3])              \
        : "r"((a)[0]), "r"((a)[1]), "r"((a)[2]), "r"((a)[3]),                 \
          "r"((b)[0]), "r"((b)[1]))

// ---------- prep: split weights to padded fp16 hi/lo [n][k] ----------
__global__ void prep_kernel(const float* __restrict__ Wlay,
                            const float* __restrict__ Wout) {
    int t = blockIdx.x * blockDim.x + threadIdx.x;
    if (t < NLAYERS * HDIM * HDIM) {
        int l = t >> 14, r = t & 16383, k = r >> 7, n = r & 127;
        float w = Wlay[t];                       // [l][k][n]
        __half hi = __float2half_rn(w);
        __half lo = __float2half_rn(w - __half2float(hi));
        uint32_t off = ((uint32_t)n * W_STRIDE + (uint32_t)k) * 2;
        *(__half*)(g_Wh[l] + off) = hi;
        *(__half*)(g_Wl[l] + off) = lo;
    } else if (t < NLAYERS * HDIM * HDIM + 16 * HDIM) {
        int r = t - NLAYERS * HDIM * HDIM;       // WoutT [16][128], 9 real rows
        int j = r >> 7, k = r & 127;
        float w = (j < 9) ? Wout[k * 9 + j] : 0.f;
        __half hi = __float2half_rn(w);
        __half lo = __float2half_rn(w - __half2float(hi));
        uint32_t off = ((uint32_t)j * W_STRIDE + (uint32_t)k) * 2;
        *(__half*)(g_WoH + off) = hi;
        *(__half*)(g_WoL + off) = lo;
    }
}

// ---------- A-op on one (feature,board) column, in place over A1/A2 ----------
__device__ __forceinline__ void aop_col(unsigned char* __restrict__ a1,
                                        unsigned char* __restrict__ a2,
                                        int f, int mbase) {
    float Trow[9][3], Tcol[3][9];
#pragma unroll
    for (int i = 0; i < 9; i++) { Trow[i][0] = Trow[i][1] = Trow[i][2] = 0.f; }
#pragma unroll
    for (int j = 0; j < 9; j++) { Tcol[0][j] = Tcol[1][j] = Tcol[2][j] = 0.f; }
#pragma unroll
    for (int node = 0; node < NNODES; node++) {
        const uint32_t off = ((uint32_t)(mbase + node) * A_STRIDE + (uint32_t)f) * 2;
        float h = __half2float(*(const __half*)(a1 + off))
                + __half2float(*(const __half*)(a2 + off));
        const int i = node / 9, j = node - 9 * i;
        Trow[i][j / 3] += h;
        Tcol[i / 3][j] += h;
    }
    float RS[9], CS[9], BS[3][3];
#pragma unroll
    for (int i = 0; i < 9; i++) RS[i] = Trow[i][0] + Trow[i][1] + Trow[i][2];
#pragma unroll
    for (int j = 0; j < 9; j++) CS[j] = Tcol[0][j] + Tcol[1][j] + Tcol[2][j];
#pragma unroll
    for (int bi = 0; bi < 3; bi++)
#pragma unroll
        for (int bj = 0; bj < 3; bj++)
            BS[bi][bj] = Trow[3 * bi][bj] + Trow[3 * bi + 1][bj] + Trow[3 * bi + 2][bj];
    const float inv21 = 1.0f / 21.0f;
#pragma unroll
    for (int node = 0; node < NNODES; node++) {
        const int i = node / 9, j = node - 9 * i;
        float g = (RS[i] + CS[j] + BS[i / 3][j / 3]
                   - Trow[i][j / 3] - Tcol[i / 3][j]) * inv21;
        __half hi = __float2half_rn(g);
        __half lo = __float2half_rn(g - __half2float(hi));
        const uint32_t off = ((uint32_t)(mbase + node) * A_STRIDE + (uint32_t)f) * 2;
        *(__half*)(a1 + off) = hi;
        *(__half*)(a2 + off) = lo;
    }
}

__global__ void __launch_bounds__(256)
gnn_mma(const long long* __restrict__ xraw,
        const float* __restrict__ Win,  const float* __restrict__ bin,
        const float* __restrict__ blay, const float* __restrict__ bout,
        float* __restrict__ out) {
    extern __shared__ unsigned char smem[];
    const int t = threadIdx.x, wid = t >> 5, lane = t & 31;
    const uint32_t sbase = smem_u32(smem);

    // ---- cp.async: W layer0 + bias0 ----
    for (int i = t * 16; i < 34816; i += 4096) {
        CPA16(sbase + SM_W1 + i, g_Wh[0] + i);
        CPA16(sbase + SM_W2 + i, g_Wl[0] + i);
    }
    if (t < 32) CPA16(sbase + SM_BIAS0 + t * 16, (const unsigned char*)blay + t * 16);
    CPA_COMMIT();

    // ---- x load (int64 vs int32 robust) ----
    long long probe = (t < 162) ? xraw[t] : 0;
    const int is32 = __syncthreads_or(probe > 9 || probe < 0);
    {
        const long long gbase = (long long)blockIdx.x * BC * NNODES;
        for (int i = t; i < BC * NNODES; i += 256)
            ((int*)(smem + SM_XS))[i] =
                is32 ? ((const int*)xraw)[gbase + i] : (int)xraw[gbase + i];
    }
    for (int i = t; i < 10 * HDIM; i += 256)
        ((float*)(smem + SM_STAGE))[i] = Win[i];
    __syncthreads();

    // ---- h0 = relu(Win[x]+bin) -> (hi,lo) columns of A1/A2 ----
    const int fA = t & 127, bA = t >> 7, mbaseA = bA * 96;
    {
        const float bk = bin[fA];
        const float* Wi = (const float*)(smem + SM_STAGE);
        const int* xr = (const int*)(smem + SM_XS) + bA * NNODES;
#pragma unroll 9
        for (int node = 0; node < NNODES; node++) {
            float v = fmaxf(Wi[xr[node] * HDIM + fA] + bk, 0.f);
            __half hi = __float2half_rn(v);
            __half lo = __float2half_rn(v - __half2float(hi));
            const uint32_t off = ((uint32_t)(mbaseA + node) * A_STRIDE + (uint32_t)fA) * 2;
            *(__half*)(smem + SM_A1 + off) = hi;
            *(__half*)(smem + SM_A2 + off) = lo;
        }
    }

    // ---- GEMM geometry ----
    const int m0 = (wid & 3) * 48;           // 3 m16 tiles
    const int n0 = (wid >> 2) * 64;          // 8 n8 tiles (4 pairs)
    const uint32_t aHiB = sbase + SM_A1 +
        (((uint32_t)(m0 + (lane & 15))) * A_STRIDE + (uint32_t)((lane >> 4) * 8)) * 2;
    const uint32_t aLoB = aHiB + (SM_A2 - SM_A1);
    // paired-B ldmatrix addressing: 16 n-rows per x4
    const uint32_t bRow = (lane & 7) + ((lane >> 4) << 3);
    const uint32_t bKo  = ((lane >> 3) & 1) * 8;
    const uint32_t bPairOff = (bRow * W_STRIDE + bKo) * 2;
    const uint32_t b1B = sbase + SM_W1 + (uint32_t)n0 * (W_STRIDE * 2) + bPairOff;
    const uint32_t b2B = b1B + (SM_W2 - SM_W1);

    for (int l = 0; l < NLAYERS; l++) {
        // ---- aop (same-thread columns; for l=0 follows h0 without sync) ----
        aop_col(smem + SM_A1, smem + SM_A2, fA, mbaseA);
        CPA_WAIT0();                 // W_l landed
        __syncthreads();

        // ---- single MMA pass: hi*Whi + hi*Wlo + lo*Whi ----
        float acc[3][8][4];
#pragma unroll
        for (int ti = 0; ti < 3; ti++)
#pragma unroll
            for (int tj = 0; tj < 8; tj++)
#pragma unroll
                for (int e = 0; e < 4; e++) acc[ti][tj][e] = 0.f;

#pragma unroll
        for (int ks = 0; ks < 8; ks++) {
            const uint32_t ko = ks * 32;
            uint32_t b1[8][2], b2[8][2];
#pragma unroll
            for (int pj = 0; pj < 4; pj++) {
                uint32_t r4[4];
                LDMX4(r4, b1B + pj * (16 * W_STRIDE * 2) + ko);
                b1[2 * pj][0] = r4[0]; b1[2 * pj][1] = r4[1];
                b1[2 * pj + 1][0] = r4[2]; b1[2 * pj + 1][1] = r4[3];
                LDMX4(r4, b2B + pj * (16 * W_STRIDE * 2) + ko);
                b2[2 * pj][0] = r4[0]; b2[2 * pj][1] = r4[1];
                b2[2 * pj + 1][0] = r4[2]; b2[2 * pj + 1][1] = r4[3];
            }
#pragma unroll
            for (int ti = 0; ti < 3; ti++) {
                uint32_t ah[4], al[4];
                LDMX4(ah, aHiB + ti * (16 * A_STRIDE * 2) + ko);
                LDMX4(al, aLoB + ti * (16 * A_STRIDE * 2) + ko);
#pragma unroll
                for (int tj = 0; tj < 8; tj++) MMA16816(acc[ti][tj], ah, b1[tj]);
#pragma unroll
                for (int tj = 0; tj < 8; tj++) MMA16816(acc[ti][tj], ah, b2[tj]);
#pragma unroll
                for (int tj = 0; tj < 8; tj++) MMA16816(acc[ti][tj], al, b1[tj]);
            }
        }
        __syncthreads();             // all A/W reads done

        // ---- prefetch next W (consumed after next aop) ----
        if (l + 1 < NLAYERS) {
            for (int i = t * 16; i < 34816; i += 4096) {
                CPA16(sbase + SM_W1 + i, g_Wh[l + 1] + i);
                CPA16(sbase + SM_W2 + i, g_Wl[l + 1] + i);
            }
            if (t < 32)
                CPA16(sbase + SM_BIAS0 + ((l + 1) & 1) * 512 + t * 16,
                      (const unsigned char*)(blay + (l + 1) * HDIM) + t * 16);
        } else {
            if (t * 16 < 4352) {
                CPA16(sbase + SM_W1 + t * 16, g_WoH + t * 16);
                CPA16(sbase + SM_W2 + t * 16, g_WoL + t * 16);
            }
        }
        CPA_COMMIT();

        // ---- epilogue: h = relu(acc+b) -> (hi,lo) packed back into A1/A2 ----
        {
            const float* bias = (const float*)(smem + SM_BIAS0 + (l & 1) * 512);
#pragma unroll
            for (int ti = 0; ti < 3; ti++) {
                const int r0 = m0 + 16 * ti + (lane >> 2);
#pragma unroll
                for (int tj = 0; tj < 8; tj++) {
                    const int c0 = n0 + 8 * tj + 2 * (lane & 3);
                    const float bb0 = bias[c0], bb1 = bias[c0 + 1];
#pragma unroll
                    for (int hh = 0; hh < 2; hh++) {
                        const int r = r0 + 8 * hh;
                        const int board = r / 96, node = r - 96 * board;
                        if (node < NNODES) {
                            float v0 = fmaxf(acc[ti][tj][2 * hh] + bb0, 0.f);
                            float v1 = fmaxf(acc[ti][tj][2 * hh + 1] + bb1, 0.f);
                            __half h0 = __float2half_rn(v0);
                            __half h1 = __float2half_rn(v1);
                            __half l0 = __float2half_rn(v0 - __half2float(h0));
                            __half l1 = __float2half_rn(v1 - __half2float(h1));
                            const uint32_t off =
                                ((uint32_t)r * A_STRIDE + (uint32_t)c0) * 2;
                            *(__half2*)(smem + SM_A1 + off) = __halves2half2(h0, h1);
                            *(__half2*)(smem + SM_A2 + off) = __halves2half2(l0, l1);
                        }
                    }
                }
            }
        }
        __syncthreads();
    }

    // ---- output layer: logits = h WoutT + bout via MMA (warps 0-3) ----
    CPA_WAIT0();
    __syncthreads();
    if (wid < 4) {
        float acc[3][2][4];
#pragma unroll
        for (int ti = 0; ti < 3; ti++)
#pragma unroll
            for (int tj = 0; tj < 2; tj++)
#pragma unroll
                for (int e = 0; e < 4; e++) acc[ti][tj][e] = 0.f;
        const uint32_t ob1 = sbase + SM_W1 + bPairOff;
        const uint32_t ob2 = ob1 + (SM_W2 - SM_W1);
        const uint32_t oaHi = sbase + SM_A1 +
            (((uint32_t)(wid * 48 + (lane & 15))) * A_STRIDE + (uint32_t)((lane >> 4) * 8)) * 2;
        const uint32_t oaLo = oaHi + (SM_A2 - SM_A1);
#pragma unroll
        for (int ks = 0; ks < 8; ks++) {
            const uint32_t ko = ks * 32;
            uint32_t b1[2][2], b2[2][2], r4[4];
            LDMX4(r4, ob1 + ko);
            b1[0][0] = r4[0]; b1[0][1] = r4[1]; b1[1][0] = r4[2]; b1[1][1] = r4[3];
            LDMX4(r4, ob2 + ko);
            b2[0][0] = r4[0]; b2[0][1] = r4[1]; b2[1][0] = r4[2]; b2[1][1] = r4[3];
#pragma unroll
            for (int ti = 0; ti < 3; ti++) {
                uint32_t ah[4], al[4];
                LDMX4(ah, oaHi + ti * (16 * A_STRIDE * 2) + ko);
                LDMX4(al, oaLo + ti * (16 * A_STRIDE * 2) + ko);
#pragma unroll
                for (int tj = 0; tj < 2; tj++) {
                    MMA16816(acc[ti][tj], ah, b1[tj]);
                    MMA16816(acc[ti][tj], ah, b2[tj]);
                    MMA16816(acc[ti][tj], al, b1[tj]);
                }
            }
        }
        // stage logits
        float* stg = (float*)(smem + SM_STAGE);
#pragma unroll
        for (int ti = 0; ti < 3; ti++) {
            const int r0 = wid * 48 + 16 * ti + (lane >> 2);
#pragma unroll
            for (int tj = 0; tj < 2; tj++) {
                const int c0 = 8 * tj + 2 * (lane & 3);
#pragma unroll
                for (int hh = 0; hh < 2; hh++) {
                    const int r = r0 + 8 * hh;
                    const int board = r / 96, node = r - 96 * board;
                    if (node < NNODES) {
                        if (c0 < 9)
                            stg[board * 729 + node * 9 + c0] =
                                acc[ti][tj][2 * hh] + bout[c0];
                        if (c0 + 1 < 9)
                            stg[board * 729 + node * 9 + c0 + 1] =
                                acc[ti][tj][2 * hh + 1] + bout[c0 + 1];
                    }
                }
            }
        }
    }
    __syncthreads();

    // ---- coalesced store ----
    {
        const float* stg = (const float*)(smem + SM_STAGE);
        const long long obase = (long long)blockIdx.x * (BC * NNODES * 9);
        for (int i = t; i < BC * NNODES * 9; i += 256)
            out[obase + i] = stg[i];
    }
}

extern "C" void kernel_launch(void* const* d_in, const int* in_sizes, int n_in,
                              void* d_out, int out_size) {
    (void)in_sizes; (void)n_in; (void)out_size;
    prep_kernel<<<400, 256>>>((const float*)d_in[3], (const float*)d_in[5]);
    cudaFuncSetAttribute(gnn_mma, cudaFuncAttributeMaxDynamicSharedMemorySize, SMEM_BYTES);
    gnn_mma<<<8192 / BC, 256, SMEM_BYTES>>>(
        (const long long*)d_in[0],
        (const float*)d_in[1], (const float*)d_in[2],
        (const float*)d_in[4], (const float*)d_in[6],
        (float*)d_out);
}

// round 6
// speedup vs baseline: 2.0725x; 1.0951x over previous
#include <cuda_runtime.h>
#include <cuda_fp16.h>
#include <cstdint>

// Fused sudoku-GNN, split-fp16 HMMA. A (=h/g) stored K-MAJOR [128 k][200 m]
// so aop/h0 columns are contiguous (vector LDS/STS); A-fragments via
// ldmatrix.x4.trans. Per layer: aop (in-register inclusion-exclusion) ->
// one MMA pass (hi*Whi + hi*Wlo + lo*Whi) -> epilogue relu+split.
// Epilogue->aop synchronized per n-half with named barriers.

#define NLAYERS 6
#define HDIM    128
#define NNODES  81
#define BC      2
#define ASTB    400      // A row bytes (200 halves; 25*16B -> conflict-free)
#define WSTB    272      // W row bytes (136 halves)

// ---- smem byte offsets ----
#define SM_A1    0            // hi  [128][400] = 51200
#define SM_A2    51200        // lo
#define SM_W1    102400       // W hi [128][136] fp16 = 34816
#define SM_W2    137216
#define SM_BIAS0 172032
#define SM_BIAS1 172544
#define SM_STAGE 173056       // Win staging (5120) / logits (5832)
#define SM_XS    178944       // 162 ints
#define SMEM_BYTES 179712

__device__ __align__(16) unsigned char g_Wh[NLAYERS][34816];
__device__ __align__(16) unsigned char g_Wl[NLAYERS][34816];
__device__ __align__(16) unsigned char g_WoH[4352];   // WoutT padded [16][136]
__device__ __align__(16) unsigned char g_WoL[4352];

__device__ __forceinline__ uint32_t smem_u32(const void* p) {
    uint32_t a;
    asm("{ .reg .u64 t; cvta.to.shared.u64 t, %1; cvt.u32.u64 %0, t; }" : "=r"(a) : "l"(p));
    return a;
}
#define CPA16(dst, src) asm volatile("cp.async.cg.shared.global [%0], [%1], 16;" :: "r"(dst), "l"(src))
#define CPA_COMMIT()    asm volatile("cp.async.commit_group;" ::: "memory")
#define CPA_WAIT0()     asm volatile("cp.async.wait_group 0;" ::: "memory")
#define BARN(id)        asm volatile("bar.sync %0, %1;" :: "r"(id), "r"(128) : "memory")

#define LDMX4(r, addr)                                                        \
    asm volatile("ldmatrix.sync.aligned.m8n8.x4.shared.b16 {%0,%1,%2,%3}, [%4];" \
        : "=r"((r)[0]), "=r"((r)[1]), "=r"((r)[2]), "=r"((r)[3]) : "r"(addr))
#define LDMX4T(r, addr)                                                       \
    asm volatile("ldmatrix.sync.aligned.m8n8.x4.trans.shared.b16 {%0,%1,%2,%3}, [%4];" \
        : "=r"((r)[0]), "=r"((r)[1]), "=r"((r)[2]), "=r"((r)[3]) : "r"(addr))
#define MMA16816(d, a, b)                                                     \
    asm volatile("mma.sync.aligned.m16n8k16.row.col.f32.f16.f16.f32 "         \
        "{%0,%1,%2,%3},{%4,%5,%6,%7},{%8,%9},{%0,%1,%2,%3};"                  \
        : "+f"((d)[0]), "+f"((d)[1]), "+f"((d)[2]), "+f"((d)[3])              \
        : "r"((a)[0]), "r"((a)[1]), "r"((a)[2]), "r"((a)[3]),                 \
          "r"((b)[0]), "r"((b)[1]))

// ---------- prep: split W to fp16 hi/lo [n][k] (k-contiguous rows) ----------
__global__ void prep_kernel(const float* __restrict__ Wlay,
                            const float* __restrict__ Wout) {
    int t = blockIdx.x * blockDim.x + threadIdx.x;
    if (t < NLAYERS * HDIM * HDIM) {
        int l = t >> 14, r = t & 16383, k = r >> 7, n = r & 127;
        float w = Wlay[t];
        __half hi = __float2half_rn(w);
        __half lo = __float2half_rn(w - __half2float(hi));
        uint32_t off = (uint32_t)n * WSTB + (uint32_t)k * 2;
        *(__half*)(g_Wh[l] + off) = hi;
        *(__half*)(g_Wl[l] + off) = lo;
    } else if (t < NLAYERS * HDIM * HDIM + 16 * HDIM) {
        int r = t - NLAYERS * HDIM * HDIM;
        int j = r >> 7, k = r & 127;
        float w = (j < 9) ? Wout[k * 9 + j] : 0.f;
        __half hi = __float2half_rn(w);
        __half lo = __float2half_rn(w - __half2float(hi));
        uint32_t off = (uint32_t)j * WSTB + (uint32_t)k * 2;
        *(__half*)(g_WoH + off) = hi;
        *(__half*)(g_WoL + off) = lo;
    }
}

__global__ void __launch_bounds__(256)
gnn_mma(const long long* __restrict__ xraw,
        const float* __restrict__ Win,  const float* __restrict__ bin,
        const float* __restrict__ blay, const float* __restrict__ bout,
        float* __restrict__ out) {
    extern __shared__ unsigned char smem[];
    const int t = threadIdx.x, wid = t >> 5, lane = t & 31;
    const uint32_t sbase = smem_u32(smem);

    // ---- cp.async: W layer0 + bias0 ----
    for (int i = t * 16; i < 34816; i += 4096) {
        CPA16(sbase + SM_W1 + i, g_Wh[0] + i);
        CPA16(sbase + SM_W2 + i, g_Wl[0] + i);
    }
    if (t < 32) CPA16(sbase + SM_BIAS0 + t * 16, (const unsigned char*)blay + t * 16);
    CPA_COMMIT();

    // ---- x load (int64 vs int32 robust) ----
    long long probe = (t < 162) ? xraw[t] : 0;
    const int is32 = __syncthreads_or(probe > 9 || probe < 0);
    {
        const long long gbase = (long long)blockIdx.x * BC * NNODES;
        for (int i = t; i < BC * NNODES; i += 256)
            ((int*)(smem + SM_XS))[i] =
                is32 ? ((const int*)xraw)[gbase + i] : (int)xraw[gbase + i];
    }
    for (int i = t; i < 10 * HDIM; i += 256)
        ((float*)(smem + SM_STAGE))[i] = Win[i];
    __syncthreads();

    // ---- column ownership: warps 0-3 features 0-63, warps 4-7 features 64-127
    const int fA = (t & 63) + ((t >> 7) << 6);
    const int bA = (t >> 6) & 1;
    unsigned char* c1 = smem + SM_A1 + fA * ASTB + bA * 192;
    unsigned char* c2 = smem + SM_A2 + fA * ASTB + bA * 192;

    // ---- h0 = relu(Win[x]+bin) -> contiguous (hi,lo) column ----
    {
        const float bk = bin[fA];
        const float* Wi = (const float*)(smem + SM_STAGE);
        const int* xr = (const int*)(smem + SM_XS) + bA * NNODES;
#pragma unroll
        for (int c = 0; c < 10; c++) {
            uint32_t o1[4], o2[4];
#pragma unroll
            for (int e = 0; e < 4; e++) {
                const int n = 8 * c + 2 * e;
                float v0 = fmaxf(Wi[xr[n] * HDIM + fA] + bk, 0.f);
                float v1 = fmaxf(Wi[xr[n + 1] * HDIM + fA] + bk, 0.f);
                __half2 hh = __floats2half2_rn(v0, v1);
                float2 hf = __half22float2(hh);
                __half2 ll = __floats2half2_rn(v0 - hf.x, v1 - hf.y);
                o1[e] = *(uint32_t*)&hh;
                o2[e] = *(uint32_t*)&ll;
            }
            *(uint4*)(c1 + 16 * c) = make_uint4(o1[0], o1[1], o1[2], o1[3]);
            *(uint4*)(c2 + 16 * c) = make_uint4(o2[0], o2[1], o2[2], o2[3]);
        }
        float v = fmaxf(Wi[xr[80] * HDIM + fA] + bk, 0.f);
        __half hh = __float2half_rn(v);
        *(__half*)(c1 + 160) = hh;
        *(__half*)(c2 + 160) = __float2half_rn(v - __half2float(hh));
    }

    // ---- GEMM geometry ----
    const int m0 = (wid & 3) * 48;
    const int n0 = (wid >> 2) * 64;
    const uint32_t aLane = ((lane & 7) + ((lane >> 4) << 3)) * ASTB
                         + ((lane >> 3) & 1) * 16;
    const uint32_t aHiB = sbase + SM_A1 + aLane + (uint32_t)m0 * 2;
    const uint32_t aLoB = aHiB + (SM_A2 - SM_A1);
    const uint32_t bPairOff = ((lane & 7) + ((lane >> 4) << 3)) * WSTB
                            + (((lane >> 3) & 1) * 8) * 2;
    const uint32_t b1B = sbase + SM_W1 + (uint32_t)n0 * WSTB + bPairOff;
    const uint32_t b2B = b1B + (SM_W2 - SM_W1);
    const int mybar = 1 + (wid >> 2);

#pragma unroll 1
    for (int l = 0; l < NLAYERS; l++) {
        // ---- aop on own column (contiguous, vectorized) ----
        {
            float Trow[9][3], Tcol[3][9];
#pragma unroll
            for (int i = 0; i < 9; i++) { Trow[i][0] = Trow[i][1] = Trow[i][2] = 0.f; }
#pragma unroll
            for (int j = 0; j < 9; j++) { Tcol[0][j] = Tcol[1][j] = Tcol[2][j] = 0.f; }
#pragma unroll
            for (int c = 0; c < 10; c++) {
                uint4 u1 = *(const uint4*)(c1 + 16 * c);
                uint4 u2 = *(const uint4*)(c2 + 16 * c);
                const uint32_t w1[4] = {u1.x, u1.y, u1.z, u1.w};
                const uint32_t w2[4] = {u2.x, u2.y, u2.z, u2.w};
#pragma unroll
                for (int e = 0; e < 4; e++) {
                    float2 fh = __half22float2(*(const __half2*)&w1[e]);
                    float2 fl = __half22float2(*(const __half2*)&w2[e]);
                    const float h0v = fh.x + fl.x, h1v = fh.y + fl.y;
                    const int n = 8 * c + 2 * e;
                    { const int i = n / 9, j = n - 9 * i;
                      Trow[i][j / 3] += h0v; Tcol[i / 3][j] += h0v; }
                    { const int n1 = n + 1, i = n1 / 9, j = n1 - 9 * (n1 / 9);
                      Trow[i][j / 3] += h1v; Tcol[i / 3][j] += h1v; }
                }
            }
            {
                float h80 = __half2float(*(const __half*)(c1 + 160))
                          + __half2float(*(const __half*)(c2 + 160));
                Trow[8][2] += h80; Tcol[2][8] += h80;
            }
            float RS[9], CS[9], BS3[3][3];
#pragma unroll
            for (int i = 0; i < 9; i++) RS[i] = Trow[i][0] + Trow[i][1] + Trow[i][2];
#pragma unroll
            for (int j = 0; j < 9; j++) CS[j] = Tcol[0][j] + Tcol[1][j] + Tcol[2][j];
#pragma unroll
            for (int bi = 0; bi < 3; bi++)
#pragma unroll
                for (int bj = 0; bj < 3; bj++)
                    BS3[bi][bj] = Trow[3 * bi][bj] + Trow[3 * bi + 1][bj] + Trow[3 * bi + 2][bj];
            float PR[9][3], CC[3][9];
#pragma unroll
            for (int i = 0; i < 9; i++)
#pragma unroll
                for (int jb = 0; jb < 3; jb++)
                    PR[i][jb] = RS[i] + BS3[i / 3][jb] - Trow[i][jb];
#pragma unroll
            for (int ib = 0; ib < 3; ib++)
#pragma unroll
                for (int j = 0; j < 9; j++)
                    CC[ib][j] = CS[j] - Tcol[ib][j];
            const float inv21 = 1.0f / 21.0f;
#pragma unroll
            for (int c = 0; c < 10; c++) {
                uint32_t o1[4], o2[4];
#pragma unroll
                for (int e = 0; e < 4; e++) {
                    const int n = 8 * c + 2 * e;
                    const int i0 = n / 9, j0 = n - 9 * i0;
                    const int n1 = n + 1, i1 = n1 / 9, j1 = n1 - 9 * i1;
                    float g0 = (PR[i0][j0 / 3] + CC[i0 / 3][j0]) * inv21;
                    float g1 = (PR[i1][j1 / 3] + CC[i1 / 3][j1]) * inv21;
                    __half2 hh = __floats2half2_rn(g0, g1);
                    float2 hf = __half22float2(hh);
                    __half2 ll = __floats2half2_rn(g0 - hf.x, g1 - hf.y);
                    o1[e] = *(uint32_t*)&hh;
                    o2[e] = *(uint32_t*)&ll;
                }
                *(uint4*)(c1 + 16 * c) = make_uint4(o1[0], o1[1], o1[2], o1[3]);
                *(uint4*)(c2 + 16 * c) = make_uint4(o2[0], o2[1], o2[2], o2[3]);
            }
            {
                float g80 = (PR[8][2] + CC[2][8]) * inv21;
                __half hh = __float2half_rn(g80);
                *(__half*)(c1 + 160) = hh;
                *(__half*)(c2 + 160) = __float2half_rn(g80 - __half2float(hh));
            }
        }
        CPA_WAIT0();
        __syncthreads();

        // ---- single MMA pass: hi*Whi + hi*Wlo + lo*Whi ----
        float acc[3][8][4];
#pragma unroll
        for (int ti = 0; ti < 3; ti++)
#pragma unroll
            for (int tj = 0; tj < 8; tj++)
#pragma unroll
                for (int e = 0; e < 4; e++) acc[ti][tj][e] = 0.f;

#pragma unroll
        for (int ks = 0; ks < 8; ks++) {
            const uint32_t akOff = (uint32_t)ks * (16 * ASTB);
            const uint32_t bkOff = (uint32_t)ks * 32;
            uint32_t b1[8][2], b2[8][2];
#pragma unroll
            for (int pj = 0; pj < 4; pj++) {
                uint32_t r4[4];
                LDMX4(r4, b1B + pj * (16 * WSTB) + bkOff);
                b1[2 * pj][0] = r4[0]; b1[2 * pj][1] = r4[1];
                b1[2 * pj + 1][0] = r4[2]; b1[2 * pj + 1][1] = r4[3];
                LDMX4(r4, b2B + pj * (16 * WSTB) + bkOff);
                b2[2 * pj][0] = r4[0]; b2[2 * pj][1] = r4[1];
                b2[2 * pj + 1][0] = r4[2]; b2[2 * pj + 1][1] = r4[3];
            }
#pragma unroll
            for (int ti = 0; ti < 3; ti++) {
                uint32_t ah[4], al[4];
                LDMX4T(ah, aHiB + akOff + ti * 32);
                LDMX4T(al, aLoB + akOff + ti * 32);
#pragma unroll
                for (int tj = 0; tj < 8; tj++) MMA16816(acc[ti][tj], ah, b1[tj]);
#pragma unroll
                for (int tj = 0; tj < 8; tj++) MMA16816(acc[ti][tj], ah, b2[tj]);
#pragma unroll
                for (int tj = 0; tj < 8; tj++) MMA16816(acc[ti][tj], al, b1[tj]);
            }
        }
        __syncthreads();             // all A/W reads done

        // ---- prefetch next W ----
        if (l + 1 < NLAYERS) {
            for (int i = t * 16; i < 34816; i += 4096) {
                CPA16(sbase + SM_W1 + i, g_Wh[l + 1] + i);
                CPA16(sbase + SM_W2 + i, g_Wl[l + 1] + i);
            }
            if (t < 32)
                CPA16(sbase + SM_BIAS0 + ((l + 1) & 1) * 512 + t * 16,
                      (const unsigned char*)(blay + (l + 1) * HDIM) + t * 16);
        } else {
            if (t * 16 < 4352) {
                CPA16(sbase + SM_W1 + t * 16, g_WoH + t * 16);
                CPA16(sbase + SM_W2 + t * 16, g_WoL + t * 16);
            }
        }
        CPA_COMMIT();

        // ---- epilogue: relu(acc+b) split to (hi,lo), k-major stores ----
        {
            const float* bias = (const float*)(smem + SM_BIAS0 + (l & 1) * 512);
#pragma unroll
            for (int ti = 0; ti < 3; ti++) {
                const int rbase = m0 + 16 * ti + (lane >> 2);
#pragma unroll
                for (int tj = 0; tj < 8; tj++) {
                    const int c0 = n0 + 8 * tj + 2 * (lane & 3);
                    const float bb0 = bias[c0], bb1 = bias[c0 + 1];
#pragma unroll
                    for (int hh = 0; hh < 2; hh++) {
                        const int r = rbase + 8 * hh;
                        const int node = (r >= 96) ? r - 96 : r;
                        if (node < NNODES) {
                            float v0 = fmaxf(acc[ti][tj][2 * hh] + bb0, 0.f);
                            float v1 = fmaxf(acc[ti][tj][2 * hh + 1] + bb1, 0.f);
                            __half h0 = __float2half_rn(v0), h1 = __float2half_rn(v1);
                            __half l0 = __float2half_rn(v0 - __half2float(h0));
                            __half l1 = __float2half_rn(v1 - __half2float(h1));
                            const uint32_t off = (uint32_t)c0 * ASTB + (uint32_t)r * 2;
                            *(__half*)(smem + SM_A1 + off) = h0;
                            *(__half*)(smem + SM_A1 + off + ASTB) = h1;
                            *(__half*)(smem + SM_A2 + off) = l0;
                            *(__half*)(smem + SM_A2 + off + ASTB) = l1;
                        }
                    }
                }
            }
        }
        BARN(mybar);                 // own n-half ready for own aop columns
    }

    // ---- output layer: logits = h WoutT + bout via MMA (warps 0-3) ----
    CPA_WAIT0();
    __syncthreads();
    if (wid < 4) {
        float acc[3][2][4];
#pragma unroll
        for (int ti = 0; ti < 3; ti++)
#pragma unroll
            for (int tj = 0; tj < 2; tj++)
#pragma unroll
                for (int e = 0; e < 4; e++) acc[ti][tj][e] = 0.f;
        const uint32_t ob1 = sbase + SM_W1 + bPairOff;
        const uint32_t ob2 = ob1 + (SM_W2 - SM_W1);
        const uint32_t oaHi = sbase + SM_A1 + aLane + (uint32_t)(wid * 48) * 2;
        const uint32_t oaLo = oaHi + (SM_A2 - SM_A1);
#pragma unroll
        for (int ks = 0; ks < 8; ks++) {
            const uint32_t akOff = (uint32_t)ks * (16 * ASTB);
            const uint32_t bkOff = (uint32_t)ks * 32;
            uint32_t b1[2][2], b2[2][2], r4[4];
            LDMX4(r4, ob1 + bkOff);
            b1[0][0] = r4[0]; b1[0][1] = r4[1]; b1[1][0] = r4[2]; b1[1][1] = r4[3];
            LDMX4(r4, ob2 + bkOff);
            b2[0][0] = r4[0]; b2[0][1] = r4[1]; b2[1][0] = r4[2]; b2[1][1] = r4[3];
#pragma unroll
            for (int ti = 0; ti < 3; ti++) {
                uint32_t ah[4], al[4];
                LDMX4T(ah, oaHi + akOff + ti * 32);
                LDMX4T(al, oaLo + akOff + ti * 32);
#pragma unroll
                for (int tj = 0; tj < 2; tj++) {
                    MMA16816(acc[ti][tj], ah, b1[tj]);
                    MMA16816(acc[ti][tj], ah, b2[tj]);
                    MMA16816(acc[ti][tj], al, b1[tj]);
                }
            }
        }
        float* stg = (float*)(smem + SM_STAGE);
#pragma unroll
        for (int ti = 0; ti < 3; ti++) {
            const int rbase = wid * 48 + 16 * ti + (lane >> 2);
#pragma unroll
            for (int tj = 0; tj < 2; tj++) {
                const int c0 = 8 * tj + 2 * (lane & 3);
#pragma unroll
                for (int hh = 0; hh < 2; hh++) {
                    const int r = rbase + 8 * hh;
                    const int board = (r >= 96) ? 1 : 0;
                    const int node = r - 96 * board;
                    if (node < NNODES) {
                        if (c0 < 9)
                            stg[board * 729 + node * 9 + c0] =
                                acc[ti][tj][2 * hh] + bout[c0];
                        if (c0 + 1 < 9)
                            stg[board * 729 + node * 9 + c0 + 1] =
                                acc[ti][tj][2 * hh + 1] + bout[c0 + 1];
                    }
                }
            }
        }
    }
    __syncthreads();

    // ---- coalesced store ----
    {
        const float* stg = (const float*)(smem + SM_STAGE);
        const long long obase = (long long)blockIdx.x * (BC * NNODES * 9);
        for (int i = t; i < BC * NNODES * 9; i += 256)
            out[obase + i] = stg[i];
    }
}

extern "C" void kernel_launch(void* const* d_in, const int* in_sizes, int n_in,
                              void* d_out, int out_size) {
    (void)in_sizes; (void)n_in; (void)out_size;
    prep_kernel<<<400, 256>>>((const float*)d_in[3], (const float*)d_in[5]);
    cudaFuncSetAttribute(gnn_mma, cudaFuncAttributeMaxDynamicSharedMemorySize, SMEM_BYTES);
    gnn_mma<<<8192 / BC, 256, SMEM_BYTES>>>(
        (const long long*)d_in[0],
        (const float*)d_in[1], (const float*)d_in[2],
        (const float*)d_in[4], (const float*)d_in[6],
        (float*)d_out);
}

// round 7
// speedup vs baseline: 2.3541x; 1.1359x over previous
#include <cuda_runtime.h>
#include <cuda_fp16.h>
#include <cstdint>

// Fused sudoku-GNN, split-fp16 HMMA, 384 threads (12 warps = 3/SMSP).
// h stored fp32 in a unified A buffer whose rows ALSO host the fp16 hi/lo
// MMA-operand views (row stride 848B: fp32 [0,768), hi [0,384), lo [416,800)).
// Per layer: aop pass reads fp32 column, computes g via inclusion-exclusion,
// splits to hi/lo in place (__syncwarp read->write protect, rows are
// warp-private). MMA: 3-term hi*Whi + hi*Wlo + lo*Whi, 12 warps 3m x 4n.
// Epilogue writes relu(acc+b) as raw fp32 (no conversions). Iter 7 = identity
// split + output MMA vs zero-padded WoutT.

#define NLAYERS 6
#define HDIM    128
#define NNODES  81
#define ASTB    848      // unified A row bytes (53*16 -> conflict-free ldmatrix)
#define LO_OFF  416
#define WSTB    272      // W row bytes (17*16)

#define SM_A     0            // 128*848 = 108544
#define SM_W1    108544       // W hi [128][136] fp16 = 34816
#define SM_W2    143360
#define SM_BIAS  178176       // 2*512 ping/pong
#define SM_STAGE 179200       // Win staging (5120) / logits (5832)
#define SM_XS    185088       // 162 ints
#define SMEM_BYTES 185744

__device__ __align__(16) unsigned char g_Wh[NLAYERS][34816];
__device__ __align__(16) unsigned char g_Wl[NLAYERS][34816];
__device__ __align__(16) unsigned char g_WoH[4352];   // WoutT padded [16][136]
__device__ __align__(16) unsigned char g_WoL[4352];

__device__ __forceinline__ uint32_t smem_u32(const void* p) {
    uint32_t a;
    asm("{ .reg .u64 t; cvta.to.shared.u64 t, %1; cvt.u32.u64 %0, t; }" : "=r"(a) : "l"(p));
    return a;
}
#define CPA16(dst, src) asm volatile("cp.async.cg.shared.global [%0], [%1], 16;" :: "r"(dst), "l"(src))
#define CPA_COMMIT()    asm volatile("cp.async.commit_group;" ::: "memory")
#define CPA_WAIT0()     asm volatile("cp.async.wait_group 0;" ::: "memory")
#define BARN(id)        asm volatile("bar.sync %0, %1;" :: "r"(id), "r"(96) : "memory")

#define LDMX4(r, addr)                                                        \
    asm volatile("ldmatrix.sync.aligned.m8n8.x4.shared.b16 {%0,%1,%2,%3}, [%4];" \
        : "=r"((r)[0]), "=r"((r)[1]), "=r"((r)[2]), "=r"((r)[3]) : "r"(addr))
#define LDMX4T(r, addr)                                                       \
    asm volatile("ldmatrix.sync.aligned.m8n8.x4.trans.shared.b16 {%0,%1,%2,%3}, [%4];" \
        : "=r"((r)[0]), "=r"((r)[1]), "=r"((r)[2]), "=r"((r)[3]) : "r"(addr))
#define MMA16816(d, a, b)                                                     \
    asm volatile("mma.sync.aligned.m16n8k16.row.col.f32.f16.f16.f32 "         \
        "{%0,%1,%2,%3},{%4,%5,%6,%7},{%8,%9},{%0,%1,%2,%3};"                  \
        : "+f"((d)[0]), "+f"((d)[1]), "+f"((d)[2]), "+f"((d)[3])              \
        : "r"((a)[0]), "r"((a)[1]), "r"((a)[2]), "r"((a)[3]),                 \
          "r"((b)[0]), "r"((b)[1]))

// ---------- prep: split W to fp16 hi/lo [n][k] ----------
__global__ void prep_kernel(const float* __restrict__ Wlay,
                            const float* __restrict__ Wout) {
    int t = blockIdx.x * blockDim.x + threadIdx.x;
    if (t < NLAYERS * HDIM * HDIM) {
        int l = t >> 14, r = t & 16383, k = r >> 7, n = r & 127;
        float w = Wlay[t];
        __half hi = __float2half_rn(w);
        __half lo = __float2half_rn(w - __half2float(hi));
        uint32_t off = (uint32_t)n * WSTB + (uint32_t)k * 2;
        *(__half*)(g_Wh[l] + off) = hi;
        *(__half*)(g_Wl[l] + off) = lo;
    } else if (t < NLAYERS * HDIM * HDIM + 16 * HDIM) {
        int r = t - NLAYERS * HDIM * HDIM;
        int j = r >> 7, k = r & 127;
        float w = (j < 9) ? Wout[k * 9 + j] : 0.f;
        __half hi = __float2half_rn(w);
        __half lo = __float2half_rn(w - __half2float(hi));
        uint32_t off = (uint32_t)j * WSTB + (uint32_t)k * 2;
        *(__half*)(g_WoH + off) = hi;
        *(__half*)(g_WoL + off) = lo;
    }
}

__global__ void __launch_bounds__(384)
gnn_mma(const long long* __restrict__ xraw,
        const float* __restrict__ Win,  const float* __restrict__ bin,
        const float* __restrict__ blay, const float* __restrict__ bout,
        float* __restrict__ out) {
    extern __shared__ unsigned char smem[];
    const int t = threadIdx.x, wid = t >> 5, lane = t & 31;
    const uint32_t sbase = smem_u32(smem);

    // ---- cp.async: W layer0 + bias0 ----
    for (int i = t * 16; i < 34816; i += 384 * 16) {
        CPA16(sbase + SM_W1 + i, g_Wh[0] + i);
        CPA16(sbase + SM_W2 + i, g_Wl[0] + i);
    }
    if (t < 32) CPA16(sbase + SM_BIAS + t * 16, (const unsigned char*)blay + t * 16);
    CPA_COMMIT();

    // ---- x load (int64 vs int32 robust) ----
    long long probe = (t < 162) ? xraw[t] : 0;
    const int is32 = __syncthreads_or(probe > 9 || probe < 0);
    {
        const long long gbase = (long long)blockIdx.x * 162;
        for (int i = t; i < 162; i += 384)
            ((int*)(smem + SM_XS))[i] =
                is32 ? ((const int*)xraw)[gbase + i] : (int)xraw[gbase + i];
    }
    for (int i = t; i < 10 * HDIM; i += 384)
        ((float*)(smem + SM_STAGE))[i] = Win[i];
    __syncthreads();

    // ---- h0 = relu(Win[x]+bin) -> fp32 columns ----
    if (t < 256) {
        const int f = t & 127, b = t >> 7;
        const float bk = bin[f];
        const float* Wi = (const float*)(smem + SM_STAGE);
        const int* xr = (const int*)(smem + SM_XS) + b * NNODES;
        unsigned char* colw = smem + SM_A + f * ASTB + b * 384;
#pragma unroll 5
        for (int c = 0; c < 20; c++) {
            float4 o;
            o.x = fmaxf(Wi[xr[4 * c + 0] * HDIM + f] + bk, 0.f);
            o.y = fmaxf(Wi[xr[4 * c + 1] * HDIM + f] + bk, 0.f);
            o.z = fmaxf(Wi[xr[4 * c + 2] * HDIM + f] + bk, 0.f);
            o.w = fmaxf(Wi[xr[4 * c + 3] * HDIM + f] + bk, 0.f);
            *(float4*)(colw + 16 * c) = o;
        }
        *(float*)(colw + 320) = fmaxf(Wi[xr[80] * HDIM + f] + bk, 0.f);
    }
    __syncthreads();

    // ---- geometry: 12 warps = 3 m-groups x 4 n-groups ----
    const int mg = wid % 3, ng = wid / 3;
    const int m0e = mg * 64, n0e = ng * 32;
    // aop: first 64 threads of each 96-thread n-group; partners (f,b) adjacent lanes
    const int local = (wid % 3) * 32 + lane;        // 0..95 within group
    const int isAop = local < 64;
    const int fA = n0e + (local >> 1), bA = local & 1;
    // MMA fragment addressing
    const uint32_t rowSel = (uint32_t)((lane & 7) + ((lane >> 4) << 3));
    const uint32_t aFrag  = rowSel * ASTB + ((lane >> 3) & 1) * 16;
    const uint32_t aHiB = sbase + SM_A + aFrag + (uint32_t)m0e * 4;  // fp32 m-pos *4? no: halves! m-col bytes = m*2
    // NOTE: m columns are 2 bytes (half). Recompute properly below.
    const uint32_t aHiBase = sbase + SM_A + aFrag + (uint32_t)m0e * 2;
    const uint32_t aLoBase = aHiBase + LO_OFF;
    const uint32_t bPairOff = rowSel * WSTB + ((lane >> 3) & 1) * 16;
    const uint32_t b1B = sbase + SM_W1 + (uint32_t)n0e * WSTB + bPairOff;
    const uint32_t b2B = b1B + (SM_W2 - SM_W1);
    (void)aHiB;

#pragma unroll 1
    for (int l = 0; l < NLAYERS + 1; l++) {
        // ================= aop / split pass =================
        if (isAop) {
            unsigned char* rowp = smem + SM_A + fA * ASTB;
            const uint4* cp = (const uint4*)(rowp + bA * 384);
            unsigned char* hip = rowp + bA * 192;
            unsigned char* lop = rowp + LO_OFF + bA * 192;
            if (l < NLAYERS) {
                float Trow[9][3], Tcol[3][9];
#pragma unroll
                for (int i = 0; i < 9; i++) { Trow[i][0] = Trow[i][1] = Trow[i][2] = 0.f; }
#pragma unroll
                for (int j = 0; j < 9; j++) { Tcol[0][j] = Tcol[1][j] = Tcol[2][j] = 0.f; }
#pragma unroll
                for (int c = 0; c < 20; c++) {
                    uint4 u = cp[c];
                    float vv[4] = {__uint_as_float(u.x), __uint_as_float(u.y),
                                   __uint_as_float(u.z), __uint_as_float(u.w)};
#pragma unroll
                    for (int e = 0; e < 4; e++) {
                        const int n = 4 * c + e, i = n / 9, j = n - 9 * i;
                        Trow[i][j / 3] += vv[e];
                        Tcol[i / 3][j] += vv[e];
                    }
                }
                const float v80 = *((const float*)cp + 80);
                Trow[8][2] += v80; Tcol[2][8] += v80;

                float RS[9], CS[9], BS[3][3];
#pragma unroll
                for (int i = 0; i < 9; i++) RS[i] = Trow[i][0] + Trow[i][1] + Trow[i][2];
#pragma unroll
                for (int j = 0; j < 9; j++) CS[j] = Tcol[0][j] + Tcol[1][j] + Tcol[2][j];
#pragma unroll
                for (int bi = 0; bi < 3; bi++)
#pragma unroll
                    for (int bj = 0; bj < 3; bj++)
                        BS[bi][bj] = Trow[3 * bi][bj] + Trow[3 * bi + 1][bj] + Trow[3 * bi + 2][bj];
                const float inv21 = 1.0f / 21.0f;
                float PR[9][3], CC[3][9];
#pragma unroll
                for (int i = 0; i < 9; i++)
#pragma unroll
                    for (int jb = 0; jb < 3; jb++)
                        PR[i][jb] = (RS[i] + BS[i / 3][jb] - Trow[i][jb]) * inv21;
#pragma unroll
                for (int ib = 0; ib < 3; ib++)
#pragma unroll
                    for (int j = 0; j < 9; j++)
                        CC[ib][j] = (CS[j] - Tcol[ib][j]) * inv21;

                __syncwarp();        // all reads of warp's rows done before writes
#pragma unroll
                for (int c = 0; c < 10; c++) {
                    uint32_t oh[4], ol[4];
#pragma unroll
                    for (int e = 0; e < 4; e++) {
                        const int n = 8 * c + 2 * e;
                        const int i0 = n / 9, j0 = n - 9 * i0;
                        const int n1 = n + 1, i1 = n1 / 9, j1 = n1 - 9 * i1;
                        float g0 = PR[i0][j0 / 3] + CC[i0 / 3][j0];
                        float g1 = PR[i1][j1 / 3] + CC[i1 / 3][j1];
                        __half2 hh2 = __floats2half2_rn(g0, g1);
                        float2 hf = __half22float2(hh2);
                        __half2 ll2 = __floats2half2_rn(g0 - hf.x, g1 - hf.y);
                        oh[e] = *(uint32_t*)&hh2;
                        ol[e] = *(uint32_t*)&ll2;
                    }
                    *(uint4*)(hip + 16 * c) = make_uint4(oh[0], oh[1], oh[2], oh[3]);
                    *(uint4*)(lop + 16 * c) = make_uint4(ol[0], ol[1], ol[2], ol[3]);
                }
                {
                    float gg = PR[8][2] + CC[2][8];
                    __half hh = __float2half_rn(gg);
                    *(__half*)(hip + 160) = hh;
                    *(__half*)(lop + 160) = __float2half_rn(gg - __half2float(hh));
                }
            } else {
                // identity split for the output MMA
                uint4 u[20];
#pragma unroll
                for (int c = 0; c < 20; c++) u[c] = cp[c];
                const float v80 = *((const float*)cp + 80);
                __syncwarp();
#pragma unroll
                for (int c = 0; c < 10; c++) {
                    uint32_t oh[4], ol[4];
                    const uint32_t* uw = (const uint32_t*)&u[2 * c];
#pragma unroll
                    for (int e = 0; e < 4; e++) {
                        float g0 = __uint_as_float(uw[2 * e]);
                        float g1 = __uint_as_float(uw[2 * e + 1]);
                        __half2 hh2 = __floats2half2_rn(g0, g1);
                        float2 hf = __half22float2(hh2);
                        __half2 ll2 = __floats2half2_rn(g0 - hf.x, g1 - hf.y);
                        oh[e] = *(uint32_t*)&hh2;
                        ol[e] = *(uint32_t*)&ll2;
                    }
                    *(uint4*)(hip + 16 * c) = make_uint4(oh[0], oh[1], oh[2], oh[3]);
                    *(uint4*)(lop + 16 * c) = make_uint4(ol[0], ol[1], ol[2], ol[3]);
                }
                __half hh = __float2half_rn(v80);
                *(__half*)(hip + 160) = hh;
                *(__half*)(lop + 160) = __float2half_rn(v80 - __half2float(hh));
            }
        }
        CPA_WAIT0();
        __syncthreads();

        if (l < NLAYERS) {
            // ================= MMA: 3-term, 12 warps =================
            float acc[4][4][4];
#pragma unroll
            for (int ti = 0; ti < 4; ti++)
#pragma unroll
                for (int tj = 0; tj < 4; tj++)
#pragma unroll
                    for (int e = 0; e < 4; e++) acc[ti][tj][e] = 0.f;

#pragma unroll
            for (int ks = 0; ks < 8; ks++) {
                const uint32_t akOff = (uint32_t)ks * (16 * ASTB);
                const uint32_t bkOff = (uint32_t)ks * 32;
                uint32_t b1[4][2], b2[4][2], r4[4];
                LDMX4(r4, b1B + bkOff);
                b1[0][0] = r4[0]; b1[0][1] = r4[1]; b1[1][0] = r4[2]; b1[1][1] = r4[3];
                LDMX4(r4, b1B + 16 * WSTB + bkOff);
                b1[2][0] = r4[0]; b1[2][1] = r4[1]; b1[3][0] = r4[2]; b1[3][1] = r4[3];
                LDMX4(r4, b2B + bkOff);
                b2[0][0] = r4[0]; b2[0][1] = r4[1]; b2[1][0] = r4[2]; b2[1][1] = r4[3];
                LDMX4(r4, b2B + 16 * WSTB + bkOff);
                b2[2][0] = r4[0]; b2[2][1] = r4[1]; b2[3][0] = r4[2]; b2[3][1] = r4[3];
#pragma unroll
                for (int ti = 0; ti < 4; ti++) {
                    uint32_t ah[4], al[4];
                    LDMX4T(ah, aHiBase + akOff + ti * 32);
                    LDMX4T(al, aLoBase + akOff + ti * 32);
#pragma unroll
                    for (int tj = 0; tj < 4; tj++) MMA16816(acc[ti][tj], ah, b1[tj]);
#pragma unroll
                    for (int tj = 0; tj < 4; tj++) MMA16816(acc[ti][tj], ah, b2[tj]);
#pragma unroll
                    for (int tj = 0; tj < 4; tj++) MMA16816(acc[ti][tj], al, b1[tj]);
                }
            }
            __syncthreads();          // all A/W reads done

            // ---- prefetch next W ----
            if (l + 1 < NLAYERS) {
                for (int i = t * 16; i < 34816; i += 384 * 16) {
                    CPA16(sbase + SM_W1 + i, g_Wh[l + 1] + i);
                    CPA16(sbase + SM_W2 + i, g_Wl[l + 1] + i);
                }
                if (t < 32)
                    CPA16(sbase + SM_BIAS + ((l + 1) & 1) * 512 + t * 16,
                          (const unsigned char*)(blay + (l + 1) * HDIM) + t * 16);
            } else {
                if (t * 16 < 4352) {
                    CPA16(sbase + SM_W1 + t * 16, g_WoH + t * 16);
                    CPA16(sbase + SM_W2 + t * 16, g_WoL + t * 16);
                }
            }
            CPA_COMMIT();

            // ---- epilogue: raw fp32 relu(acc+b) stores ----
            const float* bias = (const float*)(smem + SM_BIAS + (l & 1) * 512);
#pragma unroll
            for (int ti = 0; ti < 4; ti++) {
                const int rb = m0e + 16 * ti + (lane >> 2);
#pragma unroll
                for (int tj = 0; tj < 4; tj++) {
                    const int c0 = n0e + 8 * tj + 2 * (lane & 3);
                    const float bb0 = bias[c0], bb1 = bias[c0 + 1];
#pragma unroll
                    for (int hh = 0; hh < 2; hh++) {
                        const int r = rb + 8 * hh;
                        const int node = (r >= 96) ? r - 96 : r;
                        if (node < NNODES) {
                            *(float*)(smem + SM_A + (uint32_t)c0 * ASTB + r * 4) =
                                fmaxf(acc[ti][tj][2 * hh] + bb0, 0.f);
                            *(float*)(smem + SM_A + (uint32_t)(c0 + 1) * ASTB + r * 4) =
                                fmaxf(acc[ti][tj][2 * hh + 1] + bb1, 0.f);
                        }
                    }
                }
            }
            BARN(1 + ng);            // group's rows ready for group's aop
        } else {
            // ================= output MMA (warps 0-3) =================
            float* stg = (float*)(smem + SM_STAGE);
            if (wid < 4) {
                float acc[3][2][4];
#pragma unroll
                for (int ti = 0; ti < 3; ti++)
#pragma unroll
                    for (int tj = 0; tj < 2; tj++)
#pragma unroll
                        for (int e = 0; e < 4; e++) acc[ti][tj][e] = 0.f;
                const uint32_t oaHi = sbase + SM_A + aFrag + (uint32_t)wid * 96;
                const uint32_t oaLo = oaHi + LO_OFF;
                const uint32_t ob1 = sbase + SM_W1 + bPairOff;
                const uint32_t ob2 = ob1 + (SM_W2 - SM_W1);
#pragma unroll
                for (int ks = 0; ks < 8; ks++) {
                    const uint32_t akOff = (uint32_t)ks * (16 * ASTB);
                    const uint32_t bkOff = (uint32_t)ks * 32;
                    uint32_t b1[2][2], b2[2][2], r4[4];
                    LDMX4(r4, ob1 + bkOff);
                    b1[0][0] = r4[0]; b1[0][1] = r4[1]; b1[1][0] = r4[2]; b1[1][1] = r4[3];
                    LDMX4(r4, ob2 + bkOff);
                    b2[0][0] = r4[0]; b2[0][1] = r4[1]; b2[1][0] = r4[2]; b2[1][1] = r4[3];
#pragma unroll
                    for (int ti = 0; ti < 3; ti++) {
                        uint32_t ah[4], al[4];
                        LDMX4T(ah, oaHi + akOff + ti * 32);
                        LDMX4T(al, oaLo + akOff + ti * 32);
#pragma unroll
                        for (int tj = 0; tj < 2; tj++) {
                            MMA16816(acc[ti][tj], ah, b1[tj]);
                            MMA16816(acc[ti][tj], ah, b2[tj]);
                            MMA16816(acc[ti][tj], al, b1[tj]);
                        }
                    }
                }
#pragma unroll
                for (int ti = 0; ti < 3; ti++) {
                    const int rb = wid * 48 + 16 * ti + (lane >> 2);
#pragma unroll
                    for (int tj = 0; tj < 2; tj++) {
                        const int c0 = 8 * tj + 2 * (lane & 3);
#pragma unroll
                        for (int hh = 0; hh < 2; hh++) {
                            const int r = rb + 8 * hh;
                            const int board = (r >= 96) ? 1 : 0;
                            const int node = r - 96 * board;
                            if (node < NNODES) {
                                if (c0 < 9)
                                    stg[board * 729 + node * 9 + c0] =
                                        acc[ti][tj][2 * hh] + bout[c0];
                                if (c0 + 1 < 9)
                                    stg[board * 729 + node * 9 + c0 + 1] =
                                        acc[ti][tj][2 * hh + 1] + bout[c0 + 1];
                            }
                        }
                    }
                }
            }
            __syncthreads();
            const long long obase = (long long)blockIdx.x * 1458;
            for (int i = t; i < 1458; i += 384)
                out[obase + i] = stg[i];
        }
    }
}

extern "C" void kernel_launch(void* const* d_in, const int* in_sizes, int n_in,
                              void* d_out, int out_size) {
    (void)in_sizes; (void)n_in; (void)out_size;
    prep_kernel<<<400, 256>>>((const float*)d_in[3], (const float*)d_in[5]);
    cudaFuncSetAttribute(gnn_mma, cudaFuncAttributeMaxDynamicSharedMemorySize, SMEM_BYTES);
    gnn_mma<<<4096, 384, SMEM_BYTES>>>(
        (const long long*)d_in[0],
        (const float*)d_in[1], (const float*)d_in[2],
        (const float*)d_in[4], (const float*)d_in[6],
        (float*)d_out);
}